// round 13
// baseline (speedup 1.0000x reference)
#include <cuda_runtime.h>
#include <cuda_fp16.h>
#include <cstdint>

// ---------------- problem constants ----------------
#define BATCH   2
#define NPTS    262144
#define NBLK    2
#define EPS     1e-5f

#define MTILE   192                       // computed rows per CTA
#define TJ      188                       // valid output rows per tile
#define NTILE   ((NPTS + TJ - 1) / TJ)    // 1395
#define NTHR    192                       // 6 warps: warp grid 3m x 2n, warp tile 64x32
#define ROWS_X  194                       // gathered rows: j0-3 .. j0+190

// ---------------- smem byte offsets (194-row tiles, single W buffer) ----------------
#define SM_PA    0                        // 194 ints (pad to 1024)
#define SM_AX    1024                     // x tile,  194 rows * 128B (fp16, swizzled)
#define SM_H0    25856                    // h0 tile, 194 rows * 128B
#define SM_H1    50688                    // h1 tile, 194 rows * 128B
#define SM_W     75520                    // weight buffer: 3 taps * 8192B
#define SMEM_BYTES 100096                 // 97.75 KB -> 2 CTAs/SM (16 warps/SM)

// ---------------- global scratch (no cudaMalloc) ----------------
__device__ float g_mid[(size_t)BATCH * NPTS * 64];
__device__ unsigned char g_wb[NBLK * 3 * 3 * 8192];   // fp16 weight images [b3l][tap], swizzled
__device__ float g_bias[NBLK * 3 * 64];

// ---------------- helpers ----------------
__device__ __forceinline__ unsigned smem_u32(const void* p) {
    unsigned a;
    asm("{ .reg .u64 t; cvta.to.shared.u64 t, %1; cvt.u32.u64 %0, t; }" : "=r"(a) : "l"(p));
    return a;
}
__device__ __forceinline__ void ldsm4(unsigned* r, unsigned addr) {
    asm volatile("ldmatrix.sync.aligned.m8n8.x4.shared.b16 {%0,%1,%2,%3}, [%4];"
                 : "=r"(r[0]), "=r"(r[1]), "=r"(r[2]), "=r"(r[3]) : "r"(addr));
}
__device__ __forceinline__ void mma_fp16(float* c, const unsigned* a, const unsigned* b) {
    asm volatile("mma.sync.aligned.m16n8k16.row.col.f32.f16.f16.f32 "
                 "{%0,%1,%2,%3}, {%4,%5,%6,%7}, {%8,%9}, {%0,%1,%2,%3};"
                 : "+f"(c[0]), "+f"(c[1]), "+f"(c[2]), "+f"(c[3])
                 : "r"(a[0]), "r"(a[1]), "r"(a[2]), "r"(a[3]), "r"(b[0]), "r"(b[1]));
}
__device__ __forceinline__ unsigned pack_h2(float v0, float v1) {   // v0 -> low half
    half2 h = __floats2half2_rn(v0, v1);
    return *(unsigned*)&h;
}
__device__ __forceinline__ void sts32(unsigned addr, unsigned v) {
    asm volatile("st.shared.b32 [%0], %1;" :: "r"(addr), "r"(v) : "memory");
}
__device__ __forceinline__ unsigned lds32(unsigned addr) {
    unsigned v;
    asm volatile("ld.shared.b32 %0, [%1];" : "=r"(v) : "r"(addr));
    return v;
}
__device__ __forceinline__ void sts_zero16(unsigned addr) {
    asm volatile("st.shared.v4.b32 [%0], {%1,%1,%1,%1};" :: "r"(addr), "r"(0u) : "memory");
}
// async 24KB weight image copy (1536 x 16B, 8 iters at 192 thr) + commit one group
__device__ __forceinline__ void weights_async(unsigned dst, const unsigned char* src, int tid) {
    for (int e = tid; e < 1536; e += NTHR)
        asm volatile("cp.async.cg.shared.global [%0], [%1], 16;"
                     :: "r"(dst + e * 16), "l"(src + (size_t)e * 16) : "memory");
    asm volatile("cp.async.commit_group;" ::: "memory");
}
#define CP_WAIT(n) asm volatile("cp.async.wait_group %0;" :: "n"(n) : "memory")

// ---------------- prep: fold BN, fp16 weights, pre-swizzle ----------------
// conv_w src: [blk][l][O][I][K]; image per (b3l, tap): [o row][i col] fp16,
// 128B rows, chunk-swizzle: chunk16 ^= (o & 7).
__global__ void prep_kernel(const float* __restrict__ cw, const float* __restrict__ gam,
                            const float* __restrict__ bet, const float* __restrict__ mn,
                            const float* __restrict__ vr) {
    int t = blockIdx.x * blockDim.x + threadIdx.x;
    const int NW = NBLK * 3 * 3 * 64 * 64;
    if (t < NW) {
        int i   = t & 63;
        int o   = (t >> 6) & 63;
        int tap = (t >> 12) % 3;
        int b3l = t / 12288;
        int ch  = b3l * 64 + o;
        float sc = gam[ch] * rsqrtf(vr[ch] + EPS);
        float v  = cw[(((size_t)b3l * 64 + o) * 64 + i) * 3 + tap] * sc;
        unsigned off = (unsigned)(o * 128 + (((i >> 3) ^ (o & 7)) << 4) + ((i & 7) << 1));
        size_t ib = (size_t)(b3l * 3 + tap) * 8192;
        *(unsigned short*)(g_wb + ib + off) = __half_as_ushort(__float2half_rn(v));
    }
    if (t < NBLK * 3 * 64) {
        float sc = gam[t] * rsqrtf(vr[t] + EPS);
        g_bias[t] = bet[t] - mn[t] * sc;
    }
}

// ---------------- fused block kernel (one batch element per launch) ----------------
__global__ void __launch_bounds__(NTHR, 2)
block_kernel(const float* __restrict__ xin, float* __restrict__ xout,
             const void* __restrict__ idxp, int blk, int bb) {
    extern __shared__ char smem[];
    const unsigned sbase = smem_u32(smem);
    const int tid = threadIdx.x;
    const int w   = tid >> 5;
    const int lid = tid & 31;
    const int j0  = blockIdx.x * TJ;

    int* s_pa = (int*)(smem + SM_PA);

    // index dtype detect (JAX x64 off => int32 despite astype(int64))
    const unsigned* iw = (const unsigned*)idxp;
    const bool is64 = ((iw[1] | iw[3] | iw[5] | iw[7]) == 0u);
    const long long* p64 = (const long long*)idxp;
    const int*       p32 = (const int*)idxp;

    for (int r = tid; r < ROWS_X; r += NTHR) {   // pa rows j0-3 .. j0+190 (for scatter)
        int j = j0 - 3 + r;
        int v = 0;
        if (j >= 0 && j < NPTS)
            v = is64 ? (int)p64[(size_t)bb * NPTS + j] : p32[(size_t)bb * NPTS + j];
        s_pa[r] = v;
    }

    // async weight staging for layer 0 (overlaps gather)
    weights_async(sbase + SM_W, g_wb + (size_t)(blk * 3 + 0) * 24576, tid);

    // gather x through the permutation -> fp16 AX tile (zero outside sequence).
    // pa read directly from global; unrolled in MLP batches.
    {
        const float4* x4 = (const float4*)xin;
#pragma unroll
        for (int half = 0; half < 2; half++) {
            float4 v[9];
            int    on[9];
#pragma unroll
            for (int u = 0; u < 9; u++) {
                int s  = half * 9 + u;       // slots 0..17; slot 16 partial, 17 off
                int e  = tid + s * NTHR;
                bool o = (s < 16) || (s == 16 && tid < ROWS_X * 16 - 16 * NTHR);
                int r  = e >> 4;
                int j  = j0 - 3 + r;
                bool valid = o && (j >= 0) && (j < NPTS);
                int pa = 0;
                if (valid) pa = is64 ? (int)p64[(size_t)bb * NPTS + j] : p32[(size_t)bb * NPTS + j];
                v[u] = make_float4(0.f, 0.f, 0.f, 0.f);
                if (valid) v[u] = x4[((size_t)bb * NPTS + (size_t)pa) * 16 + (e & 15)];
                on[u] = o;
            }
#pragma unroll
            for (int u = 0; u < 9; u++) {
                if (!on[u]) continue;
                int e = tid + (half * 9 + u) * NTHR;
                int r = e >> 4, c4 = e & 15;
                unsigned off = (unsigned)(r * 128 + ((((unsigned)c4 >> 1) ^ (r & 7)) << 4) + ((c4 & 1) << 3));
                *(uint2*)(smem + SM_AX + off) = make_uint2(pack_h2(v[u].x, v[u].y), pack_h2(v[u].z, v[u].w));
            }
        }
        if (tid < 32) {   // zero rows 192,193 of H0 and H1 (read-only tails)
            int buf = (tid >> 4) & 1, rr = 192 + ((tid >> 3) & 1), ch = tid & 7;
            unsigned off = (unsigned)(rr * 128 + ch * 16);
            sts_zero16(sbase + (buf ? SM_H1 : SM_H0) + off);
        }
    }
    CP_WAIT(0);                                  // layer-0 weights landed
    __syncthreads();                             // AX, s_pa, W all visible

    // 6 warps: 3 m-groups x 2 n-groups; warp tile 64 rows x 32 cols
    const int wm  = (w % 3) * 64;
    const int wn  = (w / 3) * 32;
    const int grp = lid >> 2;          // fragment row group
    const int qd  = lid & 3;           // fragment col quad
    const int lrow = ((lid >> 3) & 1) * 8 + (lid & 7);   // ldsm row within 16-block
    const int lch  = lid >> 4;                           // ldsm chunk select (0/1)

    const float* gb = g_bias + blk * 192;

    for (int l = 0; l < 3; l++) {
        const unsigned inB  = sbase + (l == 0 ? SM_AX : (l == 1 ? SM_H0 : SM_H1));
        const unsigned outB = sbase + (l == 0 ? SM_H0 : SM_H1);
        const unsigned sW   = sbase + SM_W;

        float c[4][4][4];              // [mt][nt][frag]
#pragma unroll
        for (int nt = 0; nt < 4; nt++) {
            int cb = wn + nt * 8 + 2 * qd;
            float2 bv = __ldg((const float2*)(gb + l * 64 + cb));
#pragma unroll
            for (int mt = 0; mt < 4; mt++) {
                c[mt][nt][0] = bv.x; c[mt][nt][1] = bv.y;
                c[mt][nt][2] = bv.x; c[mt][nt][3] = bv.y;
            }
        }

#pragma unroll
        for (int tap = 0; tap < 3; tap++) {
            const unsigned wt = sW + (unsigned)tap * 8192;
#pragma unroll
            for (int kc = 0; kc < 4; kc++) {
                const int CH = 2 * kc + lch;
                unsigned a[4][4];
#pragma unroll
                for (int mt = 0; mt < 4; mt++) {
                    int R  = wm + mt * 16 + tap + lrow;
                    unsigned off = (unsigned)(R * 128 + ((CH ^ (R & 7)) << 4));
                    ldsm4(a[mt], inB + off);
                }
                unsigned b[4][2];
#pragma unroll
                for (int ng = 0; ng < 2; ng++) {
                    int O  = wn + ng * 16 + lrow;
                    unsigned off = (unsigned)(O * 128 + ((CH ^ (O & 7)) << 4));
                    unsigned r4[4];
                    ldsm4(r4, wt + off);
                    b[ng * 2][0]     = r4[0]; b[ng * 2][1]     = r4[2];
                    b[ng * 2 + 1][0] = r4[1]; b[ng * 2 + 1][1] = r4[3];
                }
#pragma unroll
                for (int mt = 0; mt < 4; mt++)
#pragma unroll
                    for (int nt = 0; nt < 4; nt++)
                        mma_fp16(c[mt][nt], a[mt], b[nt]);
            }
        }

        if (l < 2) {
            __syncthreads();   // all warps done reading W(l) before overwrite
            // prefetch next layer's weights; overlaps the epilogue below
            weights_async(sbase + SM_W, g_wb + (size_t)(blk * 3 + l + 1) * 24576, tid);

            // ---- mid epilogue: relu + boundary zero, fp16 -> out buffer ----
#pragma unroll
            for (int mt = 0; mt < 4; mt++)
#pragma unroll
                for (int h = 0; h < 2; h++) {
                    int row = wm + mt * 16 + h * 8 + grp;
                    int pos = j0 - 2 + l + row;
                    bool valid = (unsigned)pos < (unsigned)NPTS;
#pragma unroll
                    for (int nt = 0; nt < 4; nt++) {
                        float v0 = c[mt][nt][h * 2];
                        float v1 = c[mt][nt][h * 2 + 1];
                        v0 = valid ? fmaxf(v0, 0.f) : 0.f;
                        v1 = valid ? fmaxf(v1, 0.f) : 0.f;
                        int cb = wn + nt * 8 + 2 * qd;
                        unsigned off = (unsigned)(row * 128 + (((cb >> 3) ^ (row & 7)) << 4) + ((cb & 7) << 1));
                        sts32(outB + off, pack_h2(v0, v1));
                    }
                }
            CP_WAIT(0);        // next layer's weights landed
            __syncthreads();   // epilogue H writes + W visible
        } else {
            // ---- final epilogue: + residual(fp16 x from AX) + relu, scatter ----
#pragma unroll
            for (int mt = 0; mt < 4; mt++)
#pragma unroll
                for (int h = 0; h < 2; h++) {
                    int row = wm + mt * 16 + h * 8 + grp;
                    if (row >= TJ) continue;
                    int pos = j0 + row;
                    if (pos >= NPTS) continue;
                    size_t obase = ((size_t)bb * NPTS + (size_t)s_pa[row + 3]) * 64;
                    int xr = row + 3;   // AX row holding x[j0+row]
#pragma unroll
                    for (int nt = 0; nt < 4; nt++) {
                        int cb = wn + nt * 8 + 2 * qd;
                        unsigned xoff = (unsigned)(xr * 128 + (((cb >> 3) ^ (xr & 7)) << 4) + ((cb & 7) << 1));
                        unsigned xb = lds32(sbase + SM_AX + xoff);
                        float2 xv = __half22float2(*(half2*)&xb);
                        float v0 = fmaxf(c[mt][nt][h * 2]     + xv.x, 0.f);
                        float v1 = fmaxf(c[mt][nt][h * 2 + 1] + xv.y, 0.f);
                        *(float2*)(xout + obase + cb) = make_float2(v0, v1);
                    }
                }
        }
    }
}

// ---------------- launch: per-batch fork-join (overlap kernel drains) ----------------
extern "C" void kernel_launch(void* const* d_in, const int* in_sizes, int n_in,
                              void* d_out, int out_size) {
    (void)in_sizes; (void)n_in; (void)out_size;
    const float* x   = (const float*)d_in[0];
    const void*  pa1 = d_in[1];
    // d_in[2] = idx_re_1 (unused: re is the inverse of pa, folded into scatter)
    const void*  pa2 = d_in[3];
    // d_in[4] = idx_re_2 (unused)
    const float* cw  = (const float*)d_in[5];
    const float* gam = (const float*)d_in[6];
    const float* bet = (const float*)d_in[7];
    const float* mn  = (const float*)d_in[8];
    const float* vr  = (const float*)d_in[9];
    float* out = (float*)d_out;

    float* mid = nullptr;
    cudaGetSymbolAddress((void**)&mid, g_mid);

    static cudaStream_t s1 = nullptr, s2 = nullptr;
    static cudaEvent_t  e0 = nullptr, e1 = nullptr, e2 = nullptr;
    static int attr_done = 0;
    if (!attr_done) {
        cudaFuncSetAttribute(block_kernel, cudaFuncAttributeMaxDynamicSharedMemorySize,
                             SMEM_BYTES);
        cudaStreamCreateWithFlags(&s1, cudaStreamNonBlocking);
        cudaStreamCreateWithFlags(&s2, cudaStreamNonBlocking);
        cudaEventCreateWithFlags(&e0, cudaEventDisableTiming);
        cudaEventCreateWithFlags(&e1, cudaEventDisableTiming);
        cudaEventCreateWithFlags(&e2, cudaEventDisableTiming);
        attr_done = 1;
    }

    const int NPREP = NBLK * 3 * 3 * 64 * 64;
    prep_kernel<<<(NPREP + 255) / 256, 256>>>(cw, gam, bet, mn, vr);

    // fork: two independent per-batch chains
    cudaEventRecord(e0, 0);
    cudaStreamWaitEvent(s1, e0, 0);
    cudaStreamWaitEvent(s2, e0, 0);

    dim3 grid(NTILE, 1);
    block_kernel<<<grid, NTHR, SMEM_BYTES, s1>>>(x,   mid, pa1, 0, 0);
    block_kernel<<<grid, NTHR, SMEM_BYTES, s1>>>(mid, out, pa2, 1, 0);
    block_kernel<<<grid, NTHR, SMEM_BYTES, s2>>>(x,   mid, pa1, 0, 1);
    block_kernel<<<grid, NTHR, SMEM_BYTES, s2>>>(mid, out, pa2, 1, 1);

    // join back to the captured origin stream
    cudaEventRecord(e1, s1);
    cudaEventRecord(e2, s2);
    cudaStreamWaitEvent(0, e1, 0);
    cudaStreamWaitEvent(0, e2, 0);
}

// round 14
// speedup vs baseline: 1.0741x; 1.0741x over previous
#include <cuda_runtime.h>
#include <cuda_fp16.h>
#include <cstdint>

// ---------------- problem constants ----------------
#define BATCH   2
#define NPTS    262144
#define NBLK    2
#define EPS     1e-5f

#define TJ      124                       // valid output rows per tile (M=128 computed)
#define NTILE   ((NPTS + TJ - 1) / TJ)    // 2115
#define NTHR    128                       // 4 warps: warp grid 2m x 2n, warp tile 64x32
#define ROWS_X  130                       // gathered rows: j0-3 .. j0+126

// ---------------- smem byte offsets (130-row tiles, single W buffer) ----------------
#define SM_PA    0                        // 130 ints (pad to 640)
#define SM_AX    640                      // x tile,  130 rows * 128B (fp16, swizzled)
#define SM_H0    17280                    // h0 tile, 130 rows * 128B
#define SM_H1    33920                    // h1 tile, 130 rows * 128B
#define SM_W     50560                    // weight buffer: 3 taps * 8192B
#define SMEM_BYTES 75136                  // 73.4 KB -> 3 CTAs/SM

// ---------------- global scratch (no cudaMalloc) ----------------
__device__ float g_mid[(size_t)BATCH * NPTS * 64];
__device__ unsigned char g_wb[NBLK * 3 * 3 * 8192];   // fp16 weight images [b3l][tap], swizzled
__device__ float g_bias[NBLK * 3 * 64];

// ---------------- helpers ----------------
__device__ __forceinline__ unsigned smem_u32(const void* p) {
    unsigned a;
    asm("{ .reg .u64 t; cvta.to.shared.u64 t, %1; cvt.u32.u64 %0, t; }" : "=r"(a) : "l"(p));
    return a;
}
__device__ __forceinline__ void ldsm4(unsigned* r, unsigned addr) {
    asm volatile("ldmatrix.sync.aligned.m8n8.x4.shared.b16 {%0,%1,%2,%3}, [%4];"
                 : "=r"(r[0]), "=r"(r[1]), "=r"(r[2]), "=r"(r[3]) : "r"(addr));
}
__device__ __forceinline__ void mma_fp16(float* c, const unsigned* a, const unsigned* b) {
    asm volatile("mma.sync.aligned.m16n8k16.row.col.f32.f16.f16.f32 "
                 "{%0,%1,%2,%3}, {%4,%5,%6,%7}, {%8,%9}, {%0,%1,%2,%3};"
                 : "+f"(c[0]), "+f"(c[1]), "+f"(c[2]), "+f"(c[3])
                 : "r"(a[0]), "r"(a[1]), "r"(a[2]), "r"(a[3]), "r"(b[0]), "r"(b[1]));
}
__device__ __forceinline__ unsigned pack_h2(float v0, float v1) {   // v0 -> low half
    half2 h = __floats2half2_rn(v0, v1);
    return *(unsigned*)&h;
}
__device__ __forceinline__ void sts32(unsigned addr, unsigned v) {
    asm volatile("st.shared.b32 [%0], %1;" :: "r"(addr), "r"(v) : "memory");
}
__device__ __forceinline__ unsigned lds32(unsigned addr) {
    unsigned v;
    asm volatile("ld.shared.b32 %0, [%1];" : "=r"(v) : "r"(addr));
    return v;
}
__device__ __forceinline__ void sts_zero16(unsigned addr) {
    asm volatile("st.shared.v4.b32 [%0], {%1,%1,%1,%1};" :: "r"(addr), "r"(0u) : "memory");
}
// async 24KB weight image copy (1536 x 16B) + commit one group
__device__ __forceinline__ void weights_async(unsigned dst, const unsigned char* src, int tid) {
    for (int e = tid; e < 1536; e += NTHR)
        asm volatile("cp.async.cg.shared.global [%0], [%1], 16;"
                     :: "r"(dst + e * 16), "l"(src + (size_t)e * 16) : "memory");
    asm volatile("cp.async.commit_group;" ::: "memory");
}
#define CP_WAIT(n) asm volatile("cp.async.wait_group %0;" :: "n"(n) : "memory")

// ---------------- prep: fold BN, fp16 weights, pre-swizzle ----------------
// conv_w src: [blk][l][O][I][K]; image per (b3l, tap): [o row][i col] fp16,
// 128B rows, chunk-swizzle: chunk16 ^= (o & 7).
__global__ void prep_kernel(const float* __restrict__ cw, const float* __restrict__ gam,
                            const float* __restrict__ bet, const float* __restrict__ mn,
                            const float* __restrict__ vr) {
    int t = blockIdx.x * blockDim.x + threadIdx.x;
    const int NW = NBLK * 3 * 3 * 64 * 64;
    if (t < NW) {
        int i   = t & 63;
        int o   = (t >> 6) & 63;
        int tap = (t >> 12) % 3;
        int b3l = t / 12288;
        int ch  = b3l * 64 + o;
        float sc = gam[ch] * rsqrtf(vr[ch] + EPS);
        float v  = cw[(((size_t)b3l * 64 + o) * 64 + i) * 3 + tap] * sc;
        unsigned off = (unsigned)(o * 128 + (((i >> 3) ^ (o & 7)) << 4) + ((i & 7) << 1));
        size_t ib = (size_t)(b3l * 3 + tap) * 8192;
        *(unsigned short*)(g_wb + ib + off) = __half_as_ushort(__float2half_rn(v));
    }
    if (t < NBLK * 3 * 64) {
        float sc = gam[t] * rsqrtf(vr[t] + EPS);
        g_bias[t] = bet[t] - mn[t] * sc;
    }
}

// ---------------- fused block kernel (one batch element per launch) ----------------
__global__ void __launch_bounds__(NTHR, 3)
block_kernel(const float* __restrict__ xin, float* __restrict__ xout,
             const void* __restrict__ idxp, int blk, int bb) {
    extern __shared__ char smem[];
    const unsigned sbase = smem_u32(smem);
    const int tid = threadIdx.x;
    const int w   = tid >> 5;
    const int lid = tid & 31;
    const int j0  = blockIdx.x * TJ;

    int* s_pa = (int*)(smem + SM_PA);

    // index dtype detect (JAX x64 off => int32 despite astype(int64))
    const unsigned* iw = (const unsigned*)idxp;
    const bool is64 = ((iw[1] | iw[3] | iw[5] | iw[7]) == 0u);
    const long long* p64 = (const long long*)idxp;
    const int*       p32 = (const int*)idxp;

    if (tid < ROWS_X) {                          // pa rows j0-3 .. j0+126 (for scatter)
        int j = j0 - 3 + tid;
        int v = 0;
        if (j >= 0 && j < NPTS)
            v = is64 ? (int)p64[(size_t)bb * NPTS + j] : p32[(size_t)bb * NPTS + j];
        s_pa[tid] = v;
    }

    // async weight staging for layer 0 (overlaps gather)
    weights_async(sbase + SM_W, g_wb + (size_t)(blk * 3 + 0) * 24576, tid);

    // gather x through the permutation -> fp16 AX tile (zero outside sequence).
    // pa read directly from global; unrolled in two MLP batches (prologue-only regs).
    {
        const float4* x4 = (const float4*)xin;
#pragma unroll
        for (int half = 0; half < 2; half++) {
            float4 v[9];
            int    on[9];
#pragma unroll
            for (int u = 0; u < 9; u++) {
                int s  = half * 9 + u;
                int e  = tid + s * NTHR;
                bool o = (s < 16) || (tid < ROWS_X * 16 - 16 * NTHR);
                int r  = e >> 4;
                int j  = j0 - 3 + r;
                bool valid = o && (j >= 0) && (j < NPTS);
                int pa = 0;
                if (valid) pa = is64 ? (int)p64[(size_t)bb * NPTS + j] : p32[(size_t)bb * NPTS + j];
                v[u] = make_float4(0.f, 0.f, 0.f, 0.f);
                if (valid) v[u] = x4[((size_t)bb * NPTS + (size_t)pa) * 16 + (e & 15)];
                on[u] = o;
            }
#pragma unroll
            for (int u = 0; u < 9; u++) {
                if (!on[u]) continue;
                int e = tid + (half * 9 + u) * NTHR;
                int r = e >> 4, c4 = e & 15;
                unsigned off = (unsigned)(r * 128 + ((((unsigned)c4 >> 1) ^ (r & 7)) << 4) + ((c4 & 1) << 3));
                *(uint2*)(smem + SM_AX + off) = make_uint2(pack_h2(v[u].x, v[u].y), pack_h2(v[u].z, v[u].w));
            }
        }
        if (tid < 32) {   // zero rows 128,129 of H0 and H1 (read-only tails)
            int buf = (tid >> 4) & 1, rr = 128 + ((tid >> 3) & 1), ch = tid & 7;
            unsigned off = (unsigned)(rr * 128 + ch * 16);
            sts_zero16(sbase + (buf ? SM_H1 : SM_H0) + off);
        }
    }
    CP_WAIT(0);                                  // layer-0 weights landed
    __syncthreads();                             // AX, s_pa, W all visible

    // 4 warps: 2 m-groups x 2 n-groups; warp tile 64 rows x 32 cols
    const int wm  = (w >> 1) * 64;
    const int wn  = (w & 1) * 32;
    const int grp = lid >> 2;          // fragment row group
    const int qd  = lid & 3;           // fragment col quad
    const int lrow = ((lid >> 3) & 1) * 8 + (lid & 7);   // ldsm row within 16-block
    const int lch  = lid >> 4;                           // ldsm chunk select (0/1)
    // hoisted B-side ldsm row bases (per n-group)
    const unsigned bO0 = (unsigned)((wn + lrow) * 128);
    const int      br7_0 = (wn + lrow) & 7;
    const unsigned bO1 = (unsigned)((wn + 16 + lrow) * 128);
    const int      br7_1 = (wn + 16 + lrow) & 7;

    const float* gb = g_bias + blk * 192;

    for (int l = 0; l < 3; l++) {
        const unsigned inB  = sbase + (l == 0 ? SM_AX : (l == 1 ? SM_H0 : SM_H1));
        const unsigned outB = sbase + (l == 0 ? SM_H0 : SM_H1);
        const unsigned sW   = sbase + SM_W;

        float c[4][4][4];              // [mt][nt][frag]
#pragma unroll
        for (int nt = 0; nt < 4; nt++) {
            int cb = wn + nt * 8 + 2 * qd;
            float2 bv = __ldg((const float2*)(gb + l * 64 + cb));
#pragma unroll
            for (int mt = 0; mt < 4; mt++) {
                c[mt][nt][0] = bv.x; c[mt][nt][1] = bv.y;
                c[mt][nt][2] = bv.x; c[mt][nt][3] = bv.y;
            }
        }

#pragma unroll
        for (int tap = 0; tap < 3; tap++) {
            const unsigned wt = sW + (unsigned)tap * 8192;
#pragma unroll
            for (int kc = 0; kc < 4; kc++) {
                const int CH = 2 * kc + lch;
                // B first: feeds all 16 MMAs of this chunk
                unsigned b[4][2];
                {
                    unsigned r4[4];
                    ldsm4(r4, wt + bO0 + (unsigned)((CH ^ br7_0) << 4));
                    b[0][0] = r4[0]; b[0][1] = r4[2];
                    b[1][0] = r4[1]; b[1][1] = r4[3];
                    ldsm4(r4, wt + bO1 + (unsigned)((CH ^ br7_1) << 4));
                    b[2][0] = r4[0]; b[2][1] = r4[2];
                    b[3][0] = r4[1]; b[3][1] = r4[3];
                }
                unsigned a[4][4];
#pragma unroll
                for (int mt = 0; mt < 4; mt++) {
                    int R  = wm + mt * 16 + tap + lrow;
                    unsigned off = (unsigned)(R * 128 + ((CH ^ (R & 7)) << 4));
                    ldsm4(a[mt], inB + off);
                }
#pragma unroll
                for (int mt = 0; mt < 4; mt++)
#pragma unroll
                    for (int nt = 0; nt < 4; nt++)
                        mma_fp16(c[mt][nt], a[mt], b[nt]);
            }
        }

        if (l < 2) {
            __syncthreads();   // all warps done reading W(l) before overwrite
            // prefetch next layer's weights; overlaps the epilogue below
            weights_async(sbase + SM_W, g_wb + (size_t)(blk * 3 + l + 1) * 24576, tid);

            // ---- mid epilogue: relu + boundary zero, fp16 -> out buffer ----
#pragma unroll
            for (int mt = 0; mt < 4; mt++)
#pragma unroll
                for (int h = 0; h < 2; h++) {
                    int row = wm + mt * 16 + h * 8 + grp;
                    int pos = j0 - 2 + l + row;
                    bool valid = (unsigned)pos < (unsigned)NPTS;
#pragma unroll
                    for (int nt = 0; nt < 4; nt++) {
                        float v0 = c[mt][nt][h * 2];
                        float v1 = c[mt][nt][h * 2 + 1];
                        v0 = valid ? fmaxf(v0, 0.f) : 0.f;
                        v1 = valid ? fmaxf(v1, 0.f) : 0.f;
                        int cb = wn + nt * 8 + 2 * qd;
                        unsigned off = (unsigned)(row * 128 + (((cb >> 3) ^ (row & 7)) << 4) + ((cb & 7) << 1));
                        sts32(outB + off, pack_h2(v0, v1));
                    }
                }
            CP_WAIT(0);        // next layer's weights landed
            __syncthreads();   // epilogue H writes + W visible
        } else {
            // ---- final epilogue: + residual(fp16 x from AX) + relu, scatter ----
#pragma unroll
            for (int mt = 0; mt < 4; mt++)
#pragma unroll
                for (int h = 0; h < 2; h++) {
                    int row = wm + mt * 16 + h * 8 + grp;
                    if (row >= TJ) continue;
                    int pos = j0 + row;
                    if (pos >= NPTS) continue;
                    size_t obase = ((size_t)bb * NPTS + (size_t)s_pa[row + 3]) * 64;
                    int xr = row + 3;   // AX row holding x[j0+row]
#pragma unroll
                    for (int nt = 0; nt < 4; nt++) {
                        int cb = wn + nt * 8 + 2 * qd;
                        unsigned xoff = (unsigned)(xr * 128 + (((cb >> 3) ^ (xr & 7)) << 4) + ((cb & 7) << 1));
                        unsigned xb = lds32(sbase + SM_AX + xoff);
                        float2 xv = __half22float2(*(half2*)&xb);
                        float v0 = fmaxf(c[mt][nt][h * 2]     + xv.x, 0.f);
                        float v1 = fmaxf(c[mt][nt][h * 2 + 1] + xv.y, 0.f);
                        *(float2*)(xout + obase + cb) = make_float2(v0, v1);
                    }
                }
        }
    }
}

// ---------------- launch: per-batch fork-join (overlap kernel drains) ----------------
extern "C" void kernel_launch(void* const* d_in, const int* in_sizes, int n_in,
                              void* d_out, int out_size) {
    (void)in_sizes; (void)n_in; (void)out_size;
    const float* x   = (const float*)d_in[0];
    const void*  pa1 = d_in[1];
    // d_in[2] = idx_re_1 (unused: re is the inverse of pa, folded into scatter)
    const void*  pa2 = d_in[3];
    // d_in[4] = idx_re_2 (unused)
    const float* cw  = (const float*)d_in[5];
    const float* gam = (const float*)d_in[6];
    const float* bet = (const float*)d_in[7];
    const float* mn  = (const float*)d_in[8];
    const float* vr  = (const float*)d_in[9];
    float* out = (float*)d_out;

    float* mid = nullptr;
    cudaGetSymbolAddress((void**)&mid, g_mid);

    static cudaStream_t s1 = nullptr, s2 = nullptr;
    static cudaEvent_t  e0 = nullptr, e1 = nullptr, e2 = nullptr;
    static int attr_done = 0;
    if (!attr_done) {
        cudaFuncSetAttribute(block_kernel, cudaFuncAttributeMaxDynamicSharedMemorySize,
                             SMEM_BYTES);
        cudaStreamCreateWithFlags(&s1, cudaStreamNonBlocking);
        cudaStreamCreateWithFlags(&s2, cudaStreamNonBlocking);
        cudaEventCreateWithFlags(&e0, cudaEventDisableTiming);
        cudaEventCreateWithFlags(&e1, cudaEventDisableTiming);
        cudaEventCreateWithFlags(&e2, cudaEventDisableTiming);
        attr_done = 1;
    }

    const int NPREP = NBLK * 3 * 3 * 64 * 64;
    prep_kernel<<<(NPREP + 255) / 256, 256>>>(cw, gam, bet, mn, vr);

    // fork: two independent per-batch chains
    cudaEventRecord(e0, 0);
    cudaStreamWaitEvent(s1, e0, 0);
    cudaStreamWaitEvent(s2, e0, 0);

    dim3 grid(NTILE, 1);
    block_kernel<<<grid, NTHR, SMEM_BYTES, s1>>>(x,   mid, pa1, 0, 0);
    block_kernel<<<grid, NTHR, SMEM_BYTES, s1>>>(mid, out, pa2, 1, 0);
    block_kernel<<<grid, NTHR, SMEM_BYTES, s2>>>(x,   mid, pa1, 0, 1);
    block_kernel<<<grid, NTHR, SMEM_BYTES, s2>>>(mid, out, pa2, 1, 1);

    // join back to the captured origin stream
    cudaEventRecord(e1, s1);
    cudaEventRecord(e2, s2);
    cudaStreamWaitEvent(0, e1, 0);
    cudaStreamWaitEvent(0, e2, 0);
}